// round 7
// baseline (speedup 1.0000x reference)
#include <cuda_runtime.h>

// Shapes fixed by the dataset:
//   x:                   [N_PTS,  N_NODES] float32
//   learned_edge_states: [N_CMP,  N_NODES] int32 (0 == EDG_NULL)
// Output: concat( new_comp_code [N_PTS,N_CMP] f32, premerge_idx [N_PTS,N_CMP] f32 )
#define N_PTS   256
#define N_NODES 1024
#define N_CMP   1024

#define THR  2.2f     // |x| filter threshold: E[count]=28.5, sd=5.2 for N(0,1)
#define CAP  64       // candidate capacity (P(count>64) ~ 1e-11)

typedef unsigned long long u64;

// Transposed mask bits: d_maskT[n*32 + cg] bit b == (edges[cg*32+b][n] != 0).
// 128 KB static scratch — L2-resident.
__device__ unsigned d_maskT[N_NODES * (N_CMP / 32)];

// ---------------------------------------------------------------------------
// Kernel 1: pack+transpose, no ballots. Warp <-> (node-chunk, comp-group,
// byte-quarter); lane = node offset; 8 coalesced LDGs build one byte.
// ---------------------------------------------------------------------------
__global__ __launch_bounds__(256)
void pack_kernel(const int* __restrict__ edges) {
    const unsigned gw   = (blockIdx.x * blockDim.x + threadIdx.x) >> 5;
    const unsigned lane = threadIdx.x & 31;
    const unsigned q    = gw & 3;          // byte quarter (comps q*8..q*8+7)
    const unsigned cg   = (gw >> 2) & 31;  // component group
    const unsigned nch  = gw >> 7;         // node chunk
    const unsigned n    = nch * 32 + lane;

    unsigned B = 0;
    #pragma unroll
    for (int r = 0; r < 8; ++r) {
        int v = edges[(cg * 32 + q * 8 + r) * N_NODES + n];
        if (v) B |= 1u << r;
    }
    ((unsigned char*)d_maskT)[(n * 32 + cg) * 4 + q] = (unsigned char)B;
}

// ---------------------------------------------------------------------------
// Kernel 2: 4 blocks per point, 128 threads each.
// filter (float4, warp-prefix compaction) -> warp0 sort -> stage -> probe.
// Key: (bits(|x|) << 10) | (1023 - n) -> max key == max value, min index.
// ---------------------------------------------------------------------------
__device__ __forceinline__ u64 u64max(u64 a, u64 b) { return a > b ? a : b; }
__device__ __forceinline__ u64 u64min(u64 a, u64 b) { return a < b ? a : b; }

// Exact per-component scan (rare path; overflow / below-threshold / empty).
__device__ __forceinline__ void exact_scan(const float* __restrict__ x,
                                           int p, unsigned cg, unsigned bit,
                                           float& code, float& fidx) {
    u64 best = 0; bool has = false;
    for (int n = 0; n < N_NODES; ++n) {
        unsigned mw = __ldg(&d_maskT[(unsigned)n * 32 + cg]);
        if ((mw >> bit) & 1u) {
            float xn = __ldg(&x[p * N_NODES + n]);
            u64 k = (((u64)__float_as_uint(fabsf(xn))) << 10)
                    | (unsigned)((N_NODES - 1) - n);
            if (!has || k > best) { best = k; has = true; }
        }
    }
    if (has) {
        code = __uint_as_float((unsigned)(best >> 10));
        fidx = (float)((N_NODES - 1) - (int)(best & 1023ull));
    } else {
        code = 0.0f; fidx = 0.0f;
    }
}

__global__ __launch_bounds__(128)
void filter_probe_kernel(const float* __restrict__ x,
                         float* __restrict__ out_code,
                         float* __restrict__ out_idx) {
    __shared__ u64      s_cand[CAP];
    __shared__ u64      s_top[32];
    __shared__ unsigned s_w[8 * 32];     // rank-words for this block's 8 cgs
    __shared__ int      s_cnt;

    const int p    = blockIdx.x >> 2;    // point
    const int q4   = blockIdx.x & 3;     // comp quarter (256 comps)
    const int t    = threadIdx.x;
    const int w    = t >> 5;
    const int lane = t & 31;

    if (t == 0) s_cnt = 0;
    __syncthreads();

    // ---- filter: 8 elements/thread via two float4 loads ----
    const float4* xr = (const float4*)(x + p * N_NODES);
    float4 v0 = __ldg(&xr[t]);
    float4 v1 = __ldg(&xr[t + 128]);

    u64 loc[8];
    int lc = 0;
    {
        float a0[4] = {v0.x, v0.y, v0.z, v0.w};
        float a1[4] = {v1.x, v1.y, v1.z, v1.w};
        #pragma unroll
        for (int j = 0; j < 4; ++j) {
            float av = fabsf(a0[j]);
            if (av > THR) {
                int n = 4 * t + j;
                loc[lc++] = (((u64)__float_as_uint(av)) << 10)
                            | (unsigned)((N_NODES - 1) - n);
            }
        }
        #pragma unroll
        for (int j = 0; j < 4; ++j) {
            float av = fabsf(a1[j]);
            if (av > THR) {
                int n = 4 * (t + 128) + j;
                loc[lc++] = (((u64)__float_as_uint(av)) << 10)
                            | (unsigned)((N_NODES - 1) - n);
            }
        }
    }

    // warp inclusive prefix sum of lc -> one shared atomic per warp
    int incl = lc;
    #pragma unroll
    for (int d = 1; d < 32; d <<= 1) {
        int nb = __shfl_up_sync(0xFFFFFFFFu, incl, d);
        if (lane >= d) incl += nb;
    }
    int excl = incl - lc;
    int tot  = __shfl_sync(0xFFFFFFFFu, incl, 31);
    int base = 0;
    if (lane == 0 && tot) base = atomicAdd(&s_cnt, tot);
    base = __shfl_sync(0xFFFFFFFFu, base, 0);
    for (int k = 0; k < lc; ++k) {
        int pos = base + excl + k;
        if (pos < CAP) s_cand[pos] = loc[k];
    }
    __syncthreads();

    const int  cnt = s_cnt;
    const bool ovf = (cnt > CAP);        // block-uniform; P ~ 1e-11

    if (!ovf) {
        // ---- warp 0: dual bitonic sort + merge -> top-32 descending ----
        if (w == 0) {
            u64 k1 = (lane      < cnt) ? s_cand[lane]      : 0ull;
            u64 k2 = (lane + 32 < cnt) ? s_cand[lane + 32] : 0ull;
            #pragma unroll
            for (int k = 2; k <= 32; k <<= 1) {
                #pragma unroll
                for (int j = k >> 1; j > 0; j >>= 1) {
                    bool dirUp = ((lane & k) == 0);
                    bool lower = ((lane & j) == 0);
                    u64 o1 = __shfl_xor_sync(0xFFFFFFFFu, k1, j);
                    u64 o2 = __shfl_xor_sync(0xFFFFFFFFu, k2, j);
                    k1 = (dirUp == lower) ? u64min(k1, o1) : u64max(k1, o1);
                    k2 = (dirUp == lower) ? u64min(k2, o2) : u64max(k2, o2);
                }
            }
            u64 a = __shfl_xor_sync(0xFFFFFFFFu, k1, 31);   // descending
            u64 m = u64max(a, k2);                          // bitonic top-32
            #pragma unroll
            for (int j = 16; j > 0; j >>= 1) {              // -> descending
                u64 o = __shfl_xor_sync(0xFFFFFFFFu, m, j);
                bool lower = ((lane & j) == 0);
                m = lower ? u64max(m, o) : u64min(m, o);
            }
            s_top[lane] = m;
        }
        __syncthreads();

        const int n_valid = cnt < 32 ? cnt : 32;

        // ---- stage: warp w serves local comp-groups {2w, 2w+1};
        //      lane kk loads the mask word for top-kk node ----
        {
            u64 keyl = s_top[lane];
            int  nl  = (N_NODES - 1) - (int)(keyl & 1023ull);
            unsigned cgA = (unsigned)(q4 * 8 + 2 * w);
            s_w[(2 * w)     * 32 + lane] = __ldg(&d_maskT[(unsigned)nl * 32 + cgA]);
            s_w[(2 * w + 1) * 32 + lane] = __ldg(&d_maskT[(unsigned)nl * 32 + cgA + 1]);
        }
        __syncthreads();

        // ---- probe: thread t owns local comps t and t+128 ----
        #pragma unroll
        for (int half = 0; half < 2; ++half) {
            const int      cl  = t + half * 128;         // local comp
            const int      c   = q4 * 256 + cl;          // global comp
            const unsigned cgl = (unsigned)cl >> 5;      // warp-uniform
            const unsigned bit = (unsigned)c & 31;

            float code, fidx;
            bool found = false;
            for (int kk = 0; kk < n_valid; ++kk) {
                unsigned wrd = s_w[cgl * 32 + kk];       // broadcast LDS
                if ((wrd >> bit) & 1u) {
                    u64 k3 = s_top[kk];
                    code = __uint_as_float((unsigned)(k3 >> 10));
                    fidx = (float)((N_NODES - 1) - (int)(k3 & 1023ull));
                    found = true;
                    break;
                }
            }
            if (!found) {
                exact_scan(x, p, (unsigned)c >> 5, bit, code, fidx);
            }
            out_code[p * N_CMP + c] = code;
            out_idx [p * N_CMP + c] = fidx;
        }
    } else {
        // overflow: exact path for every comp this thread owns
        #pragma unroll
        for (int half = 0; half < 2; ++half) {
            const int      c   = q4 * 256 + t + half * 128;
            const unsigned cg  = (unsigned)c >> 5;
            const unsigned bit = (unsigned)c & 31;
            float code, fidx;
            exact_scan(x, p, cg, bit, code, fidx);
            out_code[p * N_CMP + c] = code;
            out_idx [p * N_CMP + c] = fidx;
        }
    }
}

// ---------------------------------------------------------------------------
extern "C" void kernel_launch(void* const* d_in, const int* in_sizes, int n_in,
                              void* d_out, int out_size) {
    const float* x     = (const float*)d_in[0];
    const int*   edges = (const int*)  d_in[1];
    float*       out   = (float*)d_out;

    pack_kernel<<<512, 256>>>(edges);
    filter_probe_kernel<<<N_PTS * 4, 128>>>(x, out, out + (size_t)N_PTS * N_CMP);
}